// round 14
// baseline (speedup 1.0000x reference)
#include <cuda_runtime.h>
#include <cuda_fp16.h>
#include <cstdint>

#define NHEADS 16
#define HDIM   64
#define DMODEL 1024
#define BATCH  2
#define SEQ    2048
#define BSROWS 4096          // BATCH*SEQ
#define HP     32            // HDIM/2  (fp16 pairs per head row)
#define KPD    512           // DMODEL/2

// --- packed fp16 global scratch ---------------------------------------------
__device__ uint32_t g_x[2*BSROWS*KPD];                           // from(0)+to(1), [m][k/2]
__device__ uint32_t g_w[3*DMODEL*KPD];                           // [z][n][k/2]
__device__ uint32_t g_q[BATCH*NHEADS*SEQ*HP];                    // [bh][s][h/2]
__device__ uint32_t g_k[BATCH*NHEADS*SEQ*HP];
__device__ uint32_t g_v[BATCH*NHEADS*SEQ*HP];
__device__ unsigned char g_mflag[BATCH*16*32];   // [b][f-tile(128)][t-chunk(64)]

// ---------------------------------------------------------------------------
__device__ __forceinline__ uint32_t round_pair_h(float x, float y)
{
    __half2 h2 = __halves2half2(__float2half_rn(x), __float2half_rn(y));
    return *reinterpret_cast<uint32_t*>(&h2);
}

__device__ __forceinline__ void mma_f16(float* d,
    uint32_t a0, uint32_t a1, uint32_t a2, uint32_t a3,
    uint32_t b0, uint32_t b1)
{
    asm("mma.sync.aligned.m16n8k16.row.col.f32.f16.f16.f32 "
        "{%0,%1,%2,%3}, {%4,%5,%6,%7}, {%8,%9}, {%0,%1,%2,%3};\n"
        : "+f"(d[0]), "+f"(d[1]), "+f"(d[2]), "+f"(d[3])
        : "r"(a0), "r"(a1), "r"(a2), "r"(a3), "r"(b0), "r"(b1));
}

__device__ __forceinline__ void ldsm_x4(uint32_t& r0, uint32_t& r1,
                                        uint32_t& r2, uint32_t& r3, uint32_t addr)
{
    asm volatile("ldmatrix.sync.aligned.m8n8.x4.shared.b16 {%0,%1,%2,%3}, [%4];\n"
        : "=r"(r0), "=r"(r1), "=r"(r2), "=r"(r3) : "r"(addr));
}

__device__ __forceinline__ void ldsm_x4_trans(uint32_t& r0, uint32_t& r1,
                                              uint32_t& r2, uint32_t& r3, uint32_t addr)
{
    asm volatile("ldmatrix.sync.aligned.m8n8.x4.trans.shared.b16 {%0,%1,%2,%3}, [%4];\n"
        : "=r"(r0), "=r"(r1), "=r"(r2), "=r"(r3) : "r"(addr));
}

// ---- cp.async helpers ------------------------------------------------------
__device__ __forceinline__ void cp16(uint32_t dst_smem, const void* src)
{
    asm volatile("cp.async.cg.shared.global [%0], [%1], 16;"
                 :: "r"(dst_smem), "l"(src));
}
__device__ __forceinline__ void cp_commit()
{
    asm volatile("cp.async.commit_group;" ::: "memory");
}
__device__ __forceinline__ void cp_wait1()
{
    asm volatile("cp.async.wait_group 1;" ::: "memory");
}

// ---------------------------------------------------------------------------
// Fused prep kernel (single launch):
//   blocks [0, 8192)       : pack X rows -> fp16 pairs
//   blocks [8192, 8960)    : pack W tiles -> transposed fp16 pairs
//   blocks [8960, 9984)    : mask all-ones flags
// ---------------------------------------------------------------------------
__global__ __launch_bounds__(256) void prep_kernel(
    const float* __restrict__ from_t, const float* __restrict__ to_t,
    const float* __restrict__ Wq, const float* __restrict__ Wk,
    const float* __restrict__ Wv, const int* __restrict__ mask)
{
    __shared__ float T[64][65];
    const int bidx = blockIdx.x;

    if (bidx < 8192) {
        // --- pack X ---
        int r = bidx;
        int c4 = threadIdx.x;
        const float* src = (r < BSROWS) ? (from_t + r*DMODEL)
                                        : (to_t + (r - BSROWS)*DMODEL);
        float4 f = *(const float4*)&src[c4*4];
        *(uint2*)&g_x[r*KPD + c4*2] =
            make_uint2(round_pair_h(f.x, f.y), round_pair_h(f.z, f.w));
    } else if (bidx < 8960) {
        // --- pack W (64k x 64n tile with smem transpose) ---
        int idx = bidx - 8192;          // 0..767
        int z   = idx >> 8;             // /256
        int rem = idx & 255;
        int kt  = (rem >> 4) * 64;
        int nt  = (rem & 15) * 64;
        const float* W = (z == 0) ? Wq : (z == 1 ? Wk : Wv);

        #pragma unroll
        for (int p = 0; p < 4; p++) {
            int i2 = threadIdx.x + p*256;
            int kr = i2 >> 4;
            int c4 = (i2 & 15) * 4;
            float4 v = *(const float4*)&W[(kt+kr)*DMODEL + nt + c4];
            T[kr][c4+0] = v.x; T[kr][c4+1] = v.y;
            T[kr][c4+2] = v.z; T[kr][c4+3] = v.w;
        }
        __syncthreads();

        const int kt2 = kt >> 1;
        #pragma unroll
        for (int p = 0; p < 8; p++) {
            int o = threadIdx.x + p*256;
            int n  = o >> 5;
            int kp = o & 31;
            int gidx = (z*DMODEL + nt + n)*KPD + kt2 + kp;
            g_w[gidx] = round_pair_h(T[2*kp][n], T[2*kp+1][n]);
        }
    } else {
        // --- mask flags ---
        int idx = bidx - 8960;          // 0..1023
        int b   = idx >> 9;             // /512
        int rem = idx & 511;
        int fy  = rem >> 5;             // f-tile 0..15
        int tx  = rem & 31;             // t-chunk 0..31
        int f   = fy*128 + (threadIdx.x >> 1);
        int tc  = tx*64  + (threadIdx.x & 1)*32;
        const int4* p = (const int4*)&mask[(b*SEQ + f)*SEQ + tc];
        int ok = 1;
        #pragma unroll
        for (int i = 0; i < 8; i++) {
            int4 v = p[i];
            ok &= (v.x == 1) & (v.y == 1) & (v.z == 1) & (v.w == 1);
        }
        ok = __syncthreads_and(ok);
        if (threadIdx.x == 0)
            g_mflag[(b*16 + fy)*32 + tx] = (unsigned char)ok;
    }
}

// ---------------------------------------------------------------------------
// Kernel: QKV projection GEMM, pure fp16 (fp32 accum), depth-2 cp.async ring.
// Block 128m x 64n, 8 warps (4m x 2n), warp 32x32, K-step 32.
// Stage: X 128x20 | W 64x20 = 3840 u32; 3 stages. 3 CTAs/SM, 1 barrier/iter.
// ---------------------------------------------------------------------------
#define PSTG 3840
#define PB_H 2560

__global__ __launch_bounds__(256, 3) void qkv_proj_kernel(
    const float* __restrict__ bq, const float* __restrict__ bk,
    const float* __restrict__ bv)
{
    extern __shared__ uint32_t dsm[];

    const int z = blockIdx.z;
    const uint32_t* Xp = g_x + (z == 0 ? 0 : BSROWS*KPD);
    const uint32_t* Wp = g_w + z*DMODEL*KPD;
    const float* bias  = (z == 0) ? bq : (z == 1 ? bk : bv);
    uint32_t* dst      = (z == 0) ? g_q : (z == 1 ? g_k : g_v);

    const int m0 = blockIdx.y * 128;
    const int n0 = blockIdx.x * 64;
    const int tid  = threadIdx.x;
    const int wid  = tid >> 5;
    const int lane = tid & 31;
    const int g  = lane >> 2;
    const int tg = lane & 3;
    const int wm = (wid >> 1) * 32;
    const int wn = (wid & 1) * 32;

    const int ar = tid >> 2;          // row 0..63 (A also +64)
    const int aq = (tid & 3) * 4;     // uint4 col within 16 k-pairs

    const int koffA = (lane & 15)*20 + (lane >> 4)*4;
    const uint32_t sBase = (uint32_t)__cvta_generic_to_shared(dsm);

    auto prefetch = [&](int stage, int kq) {
        uint32_t sb = sBase + (uint32_t)(stage * PSTG) * 4u;
        cp16(sb + (ar*20 + aq)*4u,        &Xp[(m0+ar)*KPD + kq + aq]);
        cp16(sb + ((ar+64)*20 + aq)*4u,   &Xp[(m0+ar+64)*KPD + kq + aq]);
        cp16(sb + (PB_H + ar*20 + aq)*4u, &Wp[(n0+ar)*KPD + kq + aq]);
    };

    float acc[2][4][4] = {};

    // depth-2 prologue
    prefetch(0, 0);  cp_commit();
    prefetch(1, 16); cp_commit();

    for (int it = 0; it < 32; it++) {
        cp_wait1();          // all but newest group done -> stage it ready
        __syncthreads();     // all warps done reading stage (it-1)%3
        if (it + 2 < 32) prefetch((it + 2) % 3, (it + 2) * 16);
        cp_commit();         // unconditional: uniform group accounting

        const uint32_t aB = sBase + (uint32_t)((it % 3) * PSTG) * 4u;
        #pragma unroll
        for (int ks = 0; ks < 2; ks++) {
            int kb = ks * 8;
            uint32_t ah[2][4], bh[2][4];
            #pragma unroll
            for (int mi = 0; mi < 2; mi++) {
                uint32_t off = (uint32_t)((wm + mi*16)*20 + kb + koffA) * 4u;
                ldsm_x4(ah[mi][0], ah[mi][1], ah[mi][2], ah[mi][3], aB + off);
            }
            #pragma unroll
            for (int nip = 0; nip < 2; nip++) {
                uint32_t off = (uint32_t)((wn + nip*16)*20 + kb + koffA) * 4u;
                ldsm_x4(bh[nip][0], bh[nip][1], bh[nip][2], bh[nip][3], aB + PB_H*4u + off);
            }
            #pragma unroll
            for (int nip = 0; nip < 2; nip++) {
                #pragma unroll
                for (int j = 0; j < 2; j++) {
                    int ni = nip*2 + j;
                    #pragma unroll
                    for (int mi = 0; mi < 2; mi++) {
                        mma_f16(acc[mi][ni], ah[mi][0],ah[mi][1],ah[mi][2],ah[mi][3],
                                bh[nip][j], bh[nip][2+j]);
                    }
                }
            }
        }
        // no bottom barrier: next iter's top barrier guards stage reuse
    }

    __syncthreads();
    // --- epilogue: bias, round to fp16 pairs, write scratch [bh][s][h/2] ---
    const int head = n0 >> 6;
    #pragma unroll
    for (int ni = 0; ni < 4; ni++) {
        int h = wn + ni*8 + 2*tg;
        int hp = h >> 1;
        float2 b2 = *(const float2*)&bias[n0 + h];
        #pragma unroll
        for (int mi = 0; mi < 2; mi++) {
            int r0 = m0 + wm + mi*16 + g;
            int r1 = r0 + 8;
            int b0i = r0 >> 11, s0 = r0 & (SEQ-1);
            int b1i = r1 >> 11, s1 = r1 & (SEQ-1);
            size_t i0 = ((size_t)(b0i*NHEADS + head)*SEQ + s0)*HP + hp;
            size_t i1 = ((size_t)(b1i*NHEADS + head)*SEQ + s1)*HP + hp;
            dst[i0] = round_pair_h(acc[mi][ni][0] + b2.x, acc[mi][ni][1] + b2.y);
            dst[i1] = round_pair_h(acc[mi][ni][2] + b2.x, acc[mi][ni][3] + b2.y);
        }
    }
}

// ---------------------------------------------------------------------------
// Kernel: flash attention, pure fp16 (fp32 accum), depth-2 cp.async ring.
// Stage: K 64x36 | V 64x36 = 4608 u32; 3 stages.
// ---------------------------------------------------------------------------
#define ASTG 4608
#define A_VH 2304

__global__ __launch_bounds__(256, 2) void attn_kernel(
    const int* __restrict__ mask, float* __restrict__ out)
{
    extern __shared__ uint32_t asm_dsm[];

    const int f0   = blockIdx.x * 128;
    const int head = blockIdx.y;
    const int b    = blockIdx.z;
    const int bh   = b*NHEADS + head;
    const int tid  = threadIdx.x;
    const int lane = tid & 31;
    const int g  = lane >> 2;
    const int tg = lane & 3;
    const int fb = (tid >> 5) * 16;

    const int frow0 = f0 + fb + g;
    const int frow1 = frow0 + 8;

    const int koffK = ((((lane>>4)&1)*8 + (lane&7))*36 + ((lane>>3)&1)*4);
    const int koffV = ((((lane>>3)&1)*8 + (lane&7))*36 + ((lane>>4)&1)*4);

    const uint32_t sBase = (uint32_t)__cvta_generic_to_shared(asm_dsm);

    // --- preload Q fragments ---
    uint32_t qh[4][4];
    {
        const uint32_t* qp = g_q + bh*SEQ*HP;
        int q0 = frow0*HP, q1 = frow1*HP;
        #pragma unroll
        for (int ks = 0; ks < 4; ks++) {
            int kb = ks*8 + tg;
            qh[ks][0] = qp[q0 + kb];   qh[ks][1] = qp[q1 + kb];
            qh[ks][2] = qp[q0 + kb+4]; qh[ks][3] = qp[q1 + kb+4];
        }
    }

    const uint32_t* kb_g = g_k + bh*SEQ*HP;
    const uint32_t* vb_g = g_v + bh*SEQ*HP;
    const unsigned char* mfl = &g_mflag[(b*16 + blockIdx.x)*32];

    float m0 = -1e30f, m1 = -1e30f;
    float l0s = 0.0f, l1s = 0.0f;
    float O[8][4] = {};

    const int cr  = tid >> 3;        // 0..31 -> rows cr, cr+32
    const int cc4 = (tid & 7) * 4;

    auto prefetch = [&](int stage, int t0) {
        uint32_t sb = sBase + (uint32_t)(stage * ASTG) * 4u;
        cp16(sb + (cr*36 + cc4)*4u,               &kb_g[(t0+cr)*HP + cc4]);
        cp16(sb + ((cr+32)*36 + cc4)*4u,          &kb_g[(t0+cr+32)*HP + cc4]);
        cp16(sb + (A_VH + cr*36 + cc4)*4u,        &vb_g[(t0+cr)*HP + cc4]);
        cp16(sb + (A_VH + (cr+32)*36 + cc4)*4u,   &vb_g[(t0+cr+32)*HP + cc4]);
    };

    // depth-2 prologue
    prefetch(0, 0);   cp_commit();
    prefetch(1, 64);  cp_commit();

    for (int it = 0; it < SEQ/64; it++) {
        const int t0 = it * 64;
        cp_wait1();
        __syncthreads();
        if (it + 2 < SEQ/64) prefetch((it + 2) % 3, t0 + 128);
        cp_commit();

        const uint32_t sb = sBase + (uint32_t)((it % 3) * ASTG) * 4u;
        const uint32_t khB = sb;
        const uint32_t vhB = sb + A_VH*4u;

        // --- S = Q K^T ---
        float s[8][4] = {};
        #pragma unroll
        for (int ks = 0; ks < 4; ks++) {
            int kb = ks * 8;
            #pragma unroll
            for (int ntp = 0; ntp < 4; ntp++) {
                uint32_t off = (uint32_t)(ntp*16*36 + koffK + kb) * 4u;
                uint32_t k0,k1,k2,k3;
                ldsm_x4(k0,k1,k2,k3, khB + off);
                mma_f16(s[2*ntp],   qh[ks][0],qh[ks][1],qh[ks][2],qh[ks][3], k0, k1);
                mma_f16(s[2*ntp+1], qh[ks][0],qh[ks][1],qh[ks][2],qh[ks][3], k2, k3);
            }
        }

        // --- scale + mask (skippable) + chunk row max ---
        float rmax0 = -1e30f, rmax1 = -1e30f;
        if (mfl[it]) {
            #pragma unroll
            for (int nt = 0; nt < 8; nt++) {
                s[nt][0] *= 0.125f; s[nt][1] *= 0.125f;
                s[nt][2] *= 0.125f; s[nt][3] *= 0.125f;
                rmax0 = fmaxf(rmax0, fmaxf(s[nt][0], s[nt][1]));
                rmax1 = fmaxf(rmax1, fmaxf(s[nt][2], s[nt][3]));
            }
        } else {
            #pragma unroll
            for (int nt = 0; nt < 8; nt++) {
                int tc = t0 + nt*8 + 2*tg;
                int2 mk0 = *(const int2*)&mask[(b*SEQ + frow0)*SEQ + tc];
                int2 mk1 = *(const int2*)&mask[(b*SEQ + frow1)*SEQ + tc];
                s[nt][0] = s[nt][0]*0.125f + (1.0f - (float)mk0.x) * -10000.0f;
                s[nt][1] = s[nt][1]*0.125f + (1.0f - (float)mk0.y) * -10000.0f;
                s[nt][2] = s[nt][2]*0.125f + (1.0f - (float)mk1.x) * -10000.0f;
                s[nt][3] = s[nt][3]*0.125f + (1.0f - (float)mk1.y) * -10000.0f;
                rmax0 = fmaxf(rmax0, fmaxf(s[nt][0], s[nt][1]));
                rmax1 = fmaxf(rmax1, fmaxf(s[nt][2], s[nt][3]));
            }
        }
        rmax0 = fmaxf(rmax0, __shfl_xor_sync(0xffffffffu, rmax0, 1));
        rmax0 = fmaxf(rmax0, __shfl_xor_sync(0xffffffffu, rmax0, 2));
        rmax1 = fmaxf(rmax1, __shfl_xor_sync(0xffffffffu, rmax1, 1));
        rmax1 = fmaxf(rmax1, __shfl_xor_sync(0xffffffffu, rmax1, 2));

        float mn0 = fmaxf(m0, rmax0), mn1 = fmaxf(m1, rmax1);
        float a0 = __expf(m0 - mn0),  a1 = __expf(m1 - mn1);
        m0 = mn0; m1 = mn1;

        // --- exp + round P fragments to fp16 in registers ---
        uint32_t ph0[8], ph1[8];
        float ps0 = 0.0f, ps1 = 0.0f;
        #pragma unroll
        for (int nt = 0; nt < 8; nt++) {
            float p00 = __expf(s[nt][0] - mn0);
            float p01 = __expf(s[nt][1] - mn0);
            float p10 = __expf(s[nt][2] - mn1);
            float p11 = __expf(s[nt][3] - mn1);
            ps0 += p00 + p01;
            ps1 += p10 + p11;
            ph0[nt] = round_pair_h(p00, p01);
            ph1[nt] = round_pair_h(p10, p11);
        }
        ps0 += __shfl_xor_sync(0xffffffffu, ps0, 1);
        ps0 += __shfl_xor_sync(0xffffffffu, ps0, 2);
        ps1 += __shfl_xor_sync(0xffffffffu, ps1, 1);
        ps1 += __shfl_xor_sync(0xffffffffu, ps1, 2);
        l0s = l0s * a0 + ps0;
        l1s = l1s * a1 + ps1;

        #pragma unroll
        for (int ht = 0; ht < 8; ht++) {
            O[ht][0] *= a0; O[ht][1] *= a0;
            O[ht][2] *= a1; O[ht][3] *= a1;
        }

        // --- O += P V ---
        #pragma unroll
        for (int ks = 0; ks < 4; ks++) {
            uint32_t ah0 = ph0[2*ks],   ah1 = ph1[2*ks];
            uint32_t ah2 = ph0[2*ks+1], ah3 = ph1[2*ks+1];
            #pragma unroll
            for (int htp = 0; htp < 4; htp++) {
                uint32_t off = (uint32_t)(ks*16*36 + htp*8 + koffV) * 4u;
                uint32_t v0,v1,v2,v3;
                ldsm_x4_trans(v0,v1,v2,v3, vhB + off);
                mma_f16(O[2*htp],   ah0,ah1,ah2,ah3, v0, v1);
                mma_f16(O[2*htp+1], ah0,ah1,ah2,ah3, v2, v3);
            }
        }
    }

    float inv0 = 1.0f / l0s;
    float inv1 = 1.0f / l1s;
    #pragma unroll
    for (int ht = 0; ht < 8; ht++) {
        int h = ht*8 + 2*tg;
        float2 r0 = make_float2(O[ht][0]*inv0, O[ht][1]*inv0);
        float2 r1 = make_float2(O[ht][2]*inv1, O[ht][3]*inv1);
        *(float2*)&out[(b*SEQ + frow0)*DMODEL + head*HDIM + h] = r0;
        *(float2*)&out[(b*SEQ + frow1)*DMODEL + head*HDIM + h] = r1;
    }
}

// ---------------------------------------------------------------------------
extern "C" void kernel_launch(void* const* d_in, const int* in_sizes, int n_in,
                              void* d_out, int out_size)
{
    const float* from_t = (const float*)d_in[0];
    const float* to_t   = (const float*)d_in[1];
    const int*   mask   = (const int*)  d_in[2];
    const float* Wq = (const float*)d_in[3];
    const float* bq = (const float*)d_in[4];
    const float* Wk = (const float*)d_in[5];
    const float* bk = (const float*)d_in[6];
    const float* Wv = (const float*)d_in[7];
    const float* bv = (const float*)d_in[8];
    float* out = (float*)d_out;

    prep_kernel<<<9984, 256>>>(from_t, to_t, Wq, Wk, Wv, mask);

    const int proj_smem = 3 * PSTG * 4;   // 46080 B
    cudaFuncSetAttribute(qkv_proj_kernel,
                         cudaFuncAttributeMaxDynamicSharedMemorySize, proj_smem);
    dim3 pgrid(DMODEL/64, BSROWS/128, 3);
    qkv_proj_kernel<<<pgrid, 256, proj_smem>>>(bq, bk, bv);

    const int attn_smem = 3 * ASTG * 4;   // 55296 B
    cudaFuncSetAttribute(attn_kernel,
                         cudaFuncAttributeMaxDynamicSharedMemorySize, attn_smem);
    dim3 agrid(SEQ/128, NHEADS, BATCH);
    attn_kernel<<<agrid, 256, attn_smem>>>(mask, out);
}

// round 15
// speedup vs baseline: 1.0311x; 1.0311x over previous
#include <cuda_runtime.h>
#include <cuda_fp16.h>
#include <cstdint>

#define NHEADS 16
#define HDIM   64
#define DMODEL 1024
#define BATCH  2
#define SEQ    2048
#define BSROWS 4096          // BATCH*SEQ
#define HP     32            // HDIM/2  (fp16 pairs per head row)
#define KPD    512           // DMODEL/2

// --- packed fp16 global scratch ---------------------------------------------
__device__ uint32_t g_x[2*BSROWS*KPD];                           // from(0)+to(1), [m][k/2]
__device__ uint32_t g_w[3*DMODEL*KPD];                           // [z][n][k/2]
__device__ uint32_t g_q[BATCH*NHEADS*SEQ*HP];                    // [bh][s][h/2]
__device__ uint32_t g_k[BATCH*NHEADS*SEQ*HP];
__device__ uint32_t g_v[BATCH*NHEADS*SEQ*HP];
__device__ unsigned char g_mflag[BATCH*16*32];   // [b][f-tile(128)][t-chunk(64)]

// log2 domain constants (softmax computed with ex2)
#define SCALE_L2 0.18033688011111043f     // 0.125 * log2(e)
#define MASKM_L2 -14426.950408889634f     // -10000 * log2(e)

// ---------------------------------------------------------------------------
__device__ __forceinline__ uint32_t round_pair_h(float x, float y)
{
    __half2 h2 = __halves2half2(__float2half_rn(x), __float2half_rn(y));
    return *reinterpret_cast<uint32_t*>(&h2);
}

__device__ __forceinline__ float fast_exp2(float x)
{
    float r;
    asm("ex2.approx.f32 %0, %1;" : "=f"(r) : "f"(x));
    return r;
}

__device__ __forceinline__ void mma_f16(float* d,
    uint32_t a0, uint32_t a1, uint32_t a2, uint32_t a3,
    uint32_t b0, uint32_t b1)
{
    asm("mma.sync.aligned.m16n8k16.row.col.f32.f16.f16.f32 "
        "{%0,%1,%2,%3}, {%4,%5,%6,%7}, {%8,%9}, {%0,%1,%2,%3};\n"
        : "+f"(d[0]), "+f"(d[1]), "+f"(d[2]), "+f"(d[3])
        : "r"(a0), "r"(a1), "r"(a2), "r"(a3), "r"(b0), "r"(b1));
}

__device__ __forceinline__ void ldsm_x4(uint32_t& r0, uint32_t& r1,
                                        uint32_t& r2, uint32_t& r3, uint32_t addr)
{
    asm volatile("ldmatrix.sync.aligned.m8n8.x4.shared.b16 {%0,%1,%2,%3}, [%4];\n"
        : "=r"(r0), "=r"(r1), "=r"(r2), "=r"(r3) : "r"(addr));
}

__device__ __forceinline__ void ldsm_x4_trans(uint32_t& r0, uint32_t& r1,
                                              uint32_t& r2, uint32_t& r3, uint32_t addr)
{
    asm volatile("ldmatrix.sync.aligned.m8n8.x4.trans.shared.b16 {%0,%1,%2,%3}, [%4];\n"
        : "=r"(r0), "=r"(r1), "=r"(r2), "=r"(r3) : "r"(addr));
}

// ---- cp.async helpers ------------------------------------------------------
__device__ __forceinline__ void cp16(uint32_t dst_smem, const void* src)
{
    asm volatile("cp.async.cg.shared.global [%0], [%1], 16;"
                 :: "r"(dst_smem), "l"(src));
}
__device__ __forceinline__ void cp_commit()
{
    asm volatile("cp.async.commit_group;" ::: "memory");
}
__device__ __forceinline__ void cp_wait1()
{
    asm volatile("cp.async.wait_group 1;" ::: "memory");
}

// ---------------------------------------------------------------------------
// Fused prep kernel (single launch):
//   blocks [0, 4096)       : pack X, 2 rows/block (MLP 2)
//   blocks [4096, 4864)    : pack W tiles -> transposed fp16 pairs
//   blocks [4864, 5888)    : mask all-ones flags
// ---------------------------------------------------------------------------
__global__ __launch_bounds__(256) void prep_kernel(
    const float* __restrict__ from_t, const float* __restrict__ to_t,
    const float* __restrict__ Wq, const float* __restrict__ Wk,
    const float* __restrict__ Wv, const int* __restrict__ mask)
{
    __shared__ float T[64][65];
    const int bidx = blockIdx.x;

    if (bidx < 4096) {
        // --- pack X: rows 2*bidx, 2*bidx+1 ---
        int c4 = threadIdx.x;
        #pragma unroll
        for (int rr = 0; rr < 2; rr++) {
            int r = bidx*2 + rr;
            const float* src = (r < BSROWS) ? (from_t + r*DMODEL)
                                            : (to_t + (r - BSROWS)*DMODEL);
            float4 f = *(const float4*)&src[c4*4];
            *(uint2*)&g_x[r*KPD + c4*2] =
                make_uint2(round_pair_h(f.x, f.y), round_pair_h(f.z, f.w));
        }
    } else if (bidx < 4864) {
        // --- pack W (64k x 64n tile with smem transpose) ---
        int idx = bidx - 4096;          // 0..767
        int z   = idx >> 8;             // /256
        int rem = idx & 255;
        int kt  = (rem >> 4) * 64;
        int nt  = (rem & 15) * 64;
        const float* W = (z == 0) ? Wq : (z == 1 ? Wk : Wv);

        #pragma unroll
        for (int p = 0; p < 4; p++) {
            int i2 = threadIdx.x + p*256;
            int kr = i2 >> 4;
            int c4 = (i2 & 15) * 4;
            float4 v = *(const float4*)&W[(kt+kr)*DMODEL + nt + c4];
            T[kr][c4+0] = v.x; T[kr][c4+1] = v.y;
            T[kr][c4+2] = v.z; T[kr][c4+3] = v.w;
        }
        __syncthreads();

        const int kt2 = kt >> 1;
        #pragma unroll
        for (int p = 0; p < 8; p++) {
            int o = threadIdx.x + p*256;
            int n  = o >> 5;
            int kp = o & 31;
            int gidx = (z*DMODEL + nt + n)*KPD + kt2 + kp;
            g_w[gidx] = round_pair_h(T[2*kp][n], T[2*kp+1][n]);
        }
    } else {
        // --- mask flags ---
        int idx = bidx - 4864;          // 0..1023
        int b   = idx >> 9;             // /512
        int rem = idx & 511;
        int fy  = rem >> 5;             // f-tile 0..15
        int tx  = rem & 31;             // t-chunk 0..31
        int f   = fy*128 + (threadIdx.x >> 1);
        int tc  = tx*64  + (threadIdx.x & 1)*32;
        const int4* p = (const int4*)&mask[(b*SEQ + f)*SEQ + tc];
        int ok = 1;
        #pragma unroll
        for (int i = 0; i < 8; i++) {
            int4 v = p[i];
            ok &= (v.x == 1) & (v.y == 1) & (v.z == 1) & (v.w == 1);
        }
        ok = __syncthreads_and(ok);
        if (threadIdx.x == 0)
            g_mflag[(b*16 + fy)*32 + tx] = (unsigned char)ok;
    }
}

// ---------------------------------------------------------------------------
// Kernel: QKV projection GEMM, pure fp16 (fp32 accum), depth-2 cp.async ring.
// Block 128m x 64n, 8 warps (4m x 2n), warp 32x32, K-step 32.
// Stage: X 128x20 | W 64x20 = 3840 u32; 3 stages. 1 barrier/iter.
// ---------------------------------------------------------------------------
#define PSTG 3840
#define PB_H 2560

__global__ __launch_bounds__(256, 3) void qkv_proj_kernel(
    const float* __restrict__ bq, const float* __restrict__ bk,
    const float* __restrict__ bv)
{
    extern __shared__ uint32_t dsm[];

    const int z = blockIdx.z;
    const uint32_t* Xp = g_x + (z == 0 ? 0 : BSROWS*KPD);
    const uint32_t* Wp = g_w + z*DMODEL*KPD;
    const float* bias  = (z == 0) ? bq : (z == 1 ? bk : bv);
    uint32_t* dst      = (z == 0) ? g_q : (z == 1 ? g_k : g_v);

    const int m0 = blockIdx.y * 128;
    const int n0 = blockIdx.x * 64;
    const int tid  = threadIdx.x;
    const int wid  = tid >> 5;
    const int lane = tid & 31;
    const int g  = lane >> 2;
    const int tg = lane & 3;
    const int wm = (wid >> 1) * 32;
    const int wn = (wid & 1) * 32;

    const int ar = tid >> 2;          // row 0..63 (A also +64)
    const int aq = (tid & 3) * 4;     // uint4 col within 16 k-pairs

    const int koffA = (lane & 15)*20 + (lane >> 4)*4;
    const uint32_t sBase = (uint32_t)__cvta_generic_to_shared(dsm);

    auto prefetch = [&](int stage, int kq) {
        uint32_t sb = sBase + (uint32_t)(stage * PSTG) * 4u;
        cp16(sb + (ar*20 + aq)*4u,        &Xp[(m0+ar)*KPD + kq + aq]);
        cp16(sb + ((ar+64)*20 + aq)*4u,   &Xp[(m0+ar+64)*KPD + kq + aq]);
        cp16(sb + (PB_H + ar*20 + aq)*4u, &Wp[(n0+ar)*KPD + kq + aq]);
    };

    float acc[2][4][4] = {};

    // depth-2 prologue
    prefetch(0, 0);  cp_commit();
    prefetch(1, 16); cp_commit();

    for (int it = 0; it < 32; it++) {
        cp_wait1();          // all but newest group done -> stage it ready
        __syncthreads();     // all warps done reading stage (it-1)%3
        if (it + 2 < 32) prefetch((it + 2) % 3, (it + 2) * 16);
        cp_commit();         // unconditional: uniform group accounting

        const uint32_t aB = sBase + (uint32_t)((it % 3) * PSTG) * 4u;
        #pragma unroll
        for (int ks = 0; ks < 2; ks++) {
            int kb = ks * 8;
            uint32_t ah[2][4], bh[2][4];
            #pragma unroll
            for (int mi = 0; mi < 2; mi++) {
                uint32_t off = (uint32_t)((wm + mi*16)*20 + kb + koffA) * 4u;
                ldsm_x4(ah[mi][0], ah[mi][1], ah[mi][2], ah[mi][3], aB + off);
            }
            #pragma unroll
            for (int nip = 0; nip < 2; nip++) {
                uint32_t off = (uint32_t)((wn + nip*16)*20 + kb + koffA) * 4u;
                ldsm_x4(bh[nip][0], bh[nip][1], bh[nip][2], bh[nip][3], aB + PB_H*4u + off);
            }
            #pragma unroll
            for (int nip = 0; nip < 2; nip++) {
                #pragma unroll
                for (int j = 0; j < 2; j++) {
                    int ni = nip*2 + j;
                    #pragma unroll
                    for (int mi = 0; mi < 2; mi++) {
                        mma_f16(acc[mi][ni], ah[mi][0],ah[mi][1],ah[mi][2],ah[mi][3],
                                bh[nip][j], bh[nip][2+j]);
                    }
                }
            }
        }
        // no bottom barrier: next iter's top barrier guards stage reuse
    }

    __syncthreads();
    // --- epilogue: bias, round to fp16 pairs, write scratch [bh][s][h/2] ---
    const int head = n0 >> 6;
    #pragma unroll
    for (int ni = 0; ni < 4; ni++) {
        int h = wn + ni*8 + 2*tg;
        int hp = h >> 1;
        float2 b2 = *(const float2*)&bias[n0 + h];
        #pragma unroll
        for (int mi = 0; mi < 2; mi++) {
            int r0 = m0 + wm + mi*16 + g;
            int r1 = r0 + 8;
            int b0i = r0 >> 11, s0 = r0 & (SEQ-1);
            int b1i = r1 >> 11, s1 = r1 & (SEQ-1);
            size_t i0 = ((size_t)(b0i*NHEADS + head)*SEQ + s0)*HP + hp;
            size_t i1 = ((size_t)(b1i*NHEADS + head)*SEQ + s1)*HP + hp;
            dst[i0] = round_pair_h(acc[mi][ni][0] + b2.x, acc[mi][ni][1] + b2.y);
            dst[i1] = round_pair_h(acc[mi][ni][2] + b2.x, acc[mi][ni][3] + b2.y);
        }
    }
}

// ---------------------------------------------------------------------------
// Kernel: flash attention, pure fp16 (fp32 accum), depth-2 cp.async ring.
// Softmax in log2 domain (ex2.approx). Stage: K 64x36 | V 64x36 = 4608 u32.
// ---------------------------------------------------------------------------
#define ASTG 4608
#define A_VH 2304

__global__ __launch_bounds__(256, 2) void attn_kernel(
    const int* __restrict__ mask, float* __restrict__ out)
{
    extern __shared__ uint32_t asm_dsm[];

    const int f0   = blockIdx.x * 128;
    const int head = blockIdx.y;
    const int b    = blockIdx.z;
    const int bh   = b*NHEADS + head;
    const int tid  = threadIdx.x;
    const int lane = tid & 31;
    const int g  = lane >> 2;
    const int tg = lane & 3;
    const int fb = (tid >> 5) * 16;

    const int frow0 = f0 + fb + g;
    const int frow1 = frow0 + 8;

    const int koffK = ((((lane>>4)&1)*8 + (lane&7))*36 + ((lane>>3)&1)*4);
    const int koffV = ((((lane>>3)&1)*8 + (lane&7))*36 + ((lane>>4)&1)*4);

    const uint32_t sBase = (uint32_t)__cvta_generic_to_shared(asm_dsm);

    // --- preload Q fragments ---
    uint32_t qh[4][4];
    {
        const uint32_t* qp = g_q + bh*SEQ*HP;
        int q0 = frow0*HP, q1 = frow1*HP;
        #pragma unroll
        for (int ks = 0; ks < 4; ks++) {
            int kb = ks*8 + tg;
            qh[ks][0] = qp[q0 + kb];   qh[ks][1] = qp[q1 + kb];
            qh[ks][2] = qp[q0 + kb+4]; qh[ks][3] = qp[q1 + kb+4];
        }
    }

    const uint32_t* kb_g = g_k + bh*SEQ*HP;
    const uint32_t* vb_g = g_v + bh*SEQ*HP;
    const unsigned char* mfl = &g_mflag[(b*16 + blockIdx.x)*32];

    float m0 = -1e30f, m1 = -1e30f;       // log2-domain row maxes
    float l0s = 0.0f, l1s = 0.0f;
    float O[8][4] = {};

    const int cr  = tid >> 3;        // 0..31 -> rows cr, cr+32
    const int cc4 = (tid & 7) * 4;

    auto prefetch = [&](int stage, int t0) {
        uint32_t sb = sBase + (uint32_t)(stage * ASTG) * 4u;
        cp16(sb + (cr*36 + cc4)*4u,               &kb_g[(t0+cr)*HP + cc4]);
        cp16(sb + ((cr+32)*36 + cc4)*4u,          &kb_g[(t0+cr+32)*HP + cc4]);
        cp16(sb + (A_VH + cr*36 + cc4)*4u,        &vb_g[(t0+cr)*HP + cc4]);
        cp16(sb + (A_VH + (cr+32)*36 + cc4)*4u,   &vb_g[(t0+cr+32)*HP + cc4]);
    };

    // depth-2 prologue
    prefetch(0, 0);   cp_commit();
    prefetch(1, 64);  cp_commit();

    for (int it = 0; it < SEQ/64; it++) {
        const int t0 = it * 64;
        cp_wait1();
        __syncthreads();
        if (it + 2 < SEQ/64) prefetch((it + 2) % 3, t0 + 128);
        cp_commit();

        const uint32_t sb = sBase + (uint32_t)((it % 3) * ASTG) * 4u;
        const uint32_t khB = sb;
        const uint32_t vhB = sb + A_VH*4u;

        // --- S = Q K^T ---
        float s[8][4] = {};
        #pragma unroll
        for (int ks = 0; ks < 4; ks++) {
            int kb = ks * 8;
            #pragma unroll
            for (int ntp = 0; ntp < 4; ntp++) {
                uint32_t off = (uint32_t)(ntp*16*36 + koffK + kb) * 4u;
                uint32_t k0,k1,k2,k3;
                ldsm_x4(k0,k1,k2,k3, khB + off);
                mma_f16(s[2*ntp],   qh[ks][0],qh[ks][1],qh[ks][2],qh[ks][3], k0, k1);
                mma_f16(s[2*ntp+1], qh[ks][0],qh[ks][1],qh[ks][2],qh[ks][3], k2, k3);
            }
        }

        // --- log2-domain scale + mask (skippable) + chunk row max ---
        float rmax0 = -1e30f, rmax1 = -1e30f;
        if (mfl[it]) {
            #pragma unroll
            for (int nt = 0; nt < 8; nt++) {
                s[nt][0] *= SCALE_L2; s[nt][1] *= SCALE_L2;
                s[nt][2] *= SCALE_L2; s[nt][3] *= SCALE_L2;
                rmax0 = fmaxf(rmax0, fmaxf(s[nt][0], s[nt][1]));
                rmax1 = fmaxf(rmax1, fmaxf(s[nt][2], s[nt][3]));
            }
        } else {
            #pragma unroll
            for (int nt = 0; nt < 8; nt++) {
                int tc = t0 + nt*8 + 2*tg;
                int2 mk0 = *(const int2*)&mask[(b*SEQ + frow0)*SEQ + tc];
                int2 mk1 = *(const int2*)&mask[(b*SEQ + frow1)*SEQ + tc];
                s[nt][0] = s[nt][0]*SCALE_L2 + (1.0f - (float)mk0.x) * MASKM_L2;
                s[nt][1] = s[nt][1]*SCALE_L2 + (1.0f - (float)mk0.y) * MASKM_L2;
                s[nt][2] = s[nt][2]*SCALE_L2 + (1.0f - (float)mk1.x) * MASKM_L2;
                s[nt][3] = s[nt][3]*SCALE_L2 + (1.0f - (float)mk1.y) * MASKM_L2;
                rmax0 = fmaxf(rmax0, fmaxf(s[nt][0], s[nt][1]));
                rmax1 = fmaxf(rmax1, fmaxf(s[nt][2], s[nt][3]));
            }
        }
        rmax0 = fmaxf(rmax0, __shfl_xor_sync(0xffffffffu, rmax0, 1));
        rmax0 = fmaxf(rmax0, __shfl_xor_sync(0xffffffffu, rmax0, 2));
        rmax1 = fmaxf(rmax1, __shfl_xor_sync(0xffffffffu, rmax1, 1));
        rmax1 = fmaxf(rmax1, __shfl_xor_sync(0xffffffffu, rmax1, 2));

        float mn0 = fmaxf(m0, rmax0), mn1 = fmaxf(m1, rmax1);
        float a0 = fast_exp2(m0 - mn0),  a1 = fast_exp2(m1 - mn1);
        m0 = mn0; m1 = mn1;

        // --- exp2 + round P fragments to fp16 in registers ---
        uint32_t ph0[8], ph1[8];
        float ps0 = 0.0f, ps1 = 0.0f;
        #pragma unroll
        for (int nt = 0; nt < 8; nt++) {
            float p00 = fast_exp2(s[nt][0] - mn0);
            float p01 = fast_exp2(s[nt][1] - mn0);
            float p10 = fast_exp2(s[nt][2] - mn1);
            float p11 = fast_exp2(s[nt][3] - mn1);
            ps0 += p00 + p01;
            ps1 += p10 + p11;
            ph0[nt] = round_pair_h(p00, p01);
            ph1[nt] = round_pair_h(p10, p11);
        }
        ps0 += __shfl_xor_sync(0xffffffffu, ps0, 1);
        ps0 += __shfl_xor_sync(0xffffffffu, ps0, 2);
        ps1 += __shfl_xor_sync(0xffffffffu, ps1, 1);
        ps1 += __shfl_xor_sync(0xffffffffu, ps1, 2);
        l0s = l0s * a0 + ps0;
        l1s = l1s * a1 + ps1;

        #pragma unroll
        for (int ht = 0; ht < 8; ht++) {
            O[ht][0] *= a0; O[ht][1] *= a0;
            O[ht][2] *= a1; O[ht][3] *= a1;
        }

        // --- O += P V ---
        #pragma unroll
        for (int ks = 0; ks < 4; ks++) {
            uint32_t ah0 = ph0[2*ks],   ah1 = ph1[2*ks];
            uint32_t ah2 = ph0[2*ks+1], ah3 = ph1[2*ks+1];
            #pragma unroll
            for (int htp = 0; htp < 4; htp++) {
                uint32_t off = (uint32_t)(ks*16*36 + htp*8 + koffV) * 4u;
                uint32_t v0,v1,v2,v3;
                ldsm_x4_trans(v0,v1,v2,v3, vhB + off);
                mma_f16(O[2*htp],   ah0,ah1,ah2,ah3, v0, v1);
                mma_f16(O[2*htp+1], ah0,ah1,ah2,ah3, v2, v3);
            }
        }
    }

    float inv0 = 1.0f / l0s;
    float inv1 = 1.0f / l1s;
    #pragma unroll
    for (int ht = 0; ht < 8; ht++) {
        int h = ht*8 + 2*tg;
        float2 r0 = make_float2(O[ht][0]*inv0, O[ht][1]*inv0);
        float2 r1 = make_float2(O[ht][2]*inv1, O[ht][3]*inv1);
        *(float2*)&out[(b*SEQ + frow0)*DMODEL + head*HDIM + h] = r0;
        *(float2*)&out[(b*SEQ + frow1)*DMODEL + head*HDIM + h] = r1;
    }
}

// ---------------------------------------------------------------------------
extern "C" void kernel_launch(void* const* d_in, const int* in_sizes, int n_in,
                              void* d_out, int out_size)
{
    const float* from_t = (const float*)d_in[0];
    const float* to_t   = (const float*)d_in[1];
    const int*   mask   = (const int*)  d_in[2];
    const float* Wq = (const float*)d_in[3];
    const float* bq = (const float*)d_in[4];
    const float* Wk = (const float*)d_in[5];
    const float* bk = (const float*)d_in[6];
    const float* Wv = (const float*)d_in[7];
    const float* bv = (const float*)d_in[8];
    float* out = (float*)d_out;

    prep_kernel<<<5888, 256>>>(from_t, to_t, Wq, Wk, Wv, mask);

    const int proj_smem = 3 * PSTG * 4;   // 46080 B
    cudaFuncSetAttribute(qkv_proj_kernel,
                         cudaFuncAttributeMaxDynamicSharedMemorySize, proj_smem);
    dim3 pgrid(DMODEL/64, BSROWS/128, 3);
    qkv_proj_kernel<<<pgrid, 256, proj_smem>>>(bq, bk, bv);

    const int attn_smem = 3 * ASTG * 4;   // 55296 B
    cudaFuncSetAttribute(attn_kernel,
                         cudaFuncAttributeMaxDynamicSharedMemorySize, attn_smem);
    dim3 agrid(SEQ/128, NHEADS, BATCH);
    attn_kernel<<<agrid, 256, attn_smem>>>(mask, out);
}

// round 16
// speedup vs baseline: 1.0570x; 1.0251x over previous
#include <cuda_runtime.h>
#include <cuda_fp16.h>
#include <cstdint>

#define NHEADS 16
#define HDIM   64
#define DMODEL 1024
#define BATCH  2
#define SEQ    2048
#define BSROWS 4096          // BATCH*SEQ
#define HP     32            // HDIM/2  (fp16 pairs per head row)
#define KPD    512           // DMODEL/2

// --- packed fp16 global scratch ---------------------------------------------
__device__ uint32_t g_x[2*BSROWS*KPD];                           // from(0)+to(1), [m][k/2]
__device__ uint32_t g_w[3*DMODEL*KPD];                           // [z][n][k/2]
__device__ uint32_t g_q[BATCH*NHEADS*SEQ*HP];                    // [bh][s][h/2], pre-scaled
__device__ uint32_t g_k[BATCH*NHEADS*SEQ*HP];
__device__ uint32_t g_v[BATCH*NHEADS*SEQ*HP];
__device__ unsigned char g_mflag[BATCH*16*32];   // [b][f-tile(128)][t-chunk(64)]

// log2 domain constants (softmax computed with ex2; scale folded into Q)
#define SCALE_L2 0.18033688011111043f     // 0.125 * log2(e)
#define MASKM_L2 -14426.950408889634f     // -10000 * log2(e)

// ---------------------------------------------------------------------------
__device__ __forceinline__ uint32_t round_pair_h(float x, float y)
{
    __half2 h2 = __halves2half2(__float2half_rn(x), __float2half_rn(y));
    return *reinterpret_cast<uint32_t*>(&h2);
}

__device__ __forceinline__ float fast_exp2(float x)
{
    float r;
    asm("ex2.approx.f32 %0, %1;" : "=f"(r) : "f"(x));
    return r;
}

__device__ __forceinline__ void mma_f16(float* d,
    uint32_t a0, uint32_t a1, uint32_t a2, uint32_t a3,
    uint32_t b0, uint32_t b1)
{
    asm("mma.sync.aligned.m16n8k16.row.col.f32.f16.f16.f32 "
        "{%0,%1,%2,%3}, {%4,%5,%6,%7}, {%8,%9}, {%0,%1,%2,%3};\n"
        : "+f"(d[0]), "+f"(d[1]), "+f"(d[2]), "+f"(d[3])
        : "r"(a0), "r"(a1), "r"(a2), "r"(a3), "r"(b0), "r"(b1));
}

__device__ __forceinline__ void ldsm_x4(uint32_t& r0, uint32_t& r1,
                                        uint32_t& r2, uint32_t& r3, uint32_t addr)
{
    asm volatile("ldmatrix.sync.aligned.m8n8.x4.shared.b16 {%0,%1,%2,%3}, [%4];\n"
        : "=r"(r0), "=r"(r1), "=r"(r2), "=r"(r3) : "r"(addr));
}

__device__ __forceinline__ void ldsm_x4_trans(uint32_t& r0, uint32_t& r1,
                                              uint32_t& r2, uint32_t& r3, uint32_t addr)
{
    asm volatile("ldmatrix.sync.aligned.m8n8.x4.trans.shared.b16 {%0,%1,%2,%3}, [%4];\n"
        : "=r"(r0), "=r"(r1), "=r"(r2), "=r"(r3) : "r"(addr));
}

// ---- cp.async helpers ------------------------------------------------------
__device__ __forceinline__ void cp16(uint32_t dst_smem, const void* src)
{
    asm volatile("cp.async.cg.shared.global [%0], [%1], 16;"
                 :: "r"(dst_smem), "l"(src));
}
__device__ __forceinline__ void cp_commit()
{
    asm volatile("cp.async.commit_group;" ::: "memory");
}
__device__ __forceinline__ void cp_wait1()
{
    asm volatile("cp.async.wait_group 1;" ::: "memory");
}

// ---------------------------------------------------------------------------
// Fused prep kernel (single launch):
//   blocks [0, 2048)       : pack X, 4 rows/block (MLP 4)
//   blocks [2048, 2816)    : pack W tiles -> transposed fp16 pairs
//   blocks [2816, 3840)    : mask all-ones flags
// ---------------------------------------------------------------------------
__global__ __launch_bounds__(256) void prep_kernel(
    const float* __restrict__ from_t, const float* __restrict__ to_t,
    const float* __restrict__ Wq, const float* __restrict__ Wk,
    const float* __restrict__ Wv, const int* __restrict__ mask)
{
    __shared__ float T[64][65];
    const int bidx = blockIdx.x;

    if (bidx < 2048) {
        // --- pack X: rows 4*bidx .. 4*bidx+3 (independent loads -> MLP 4) ---
        int c4 = threadIdx.x;
        float4 f[4];
        #pragma unroll
        for (int rr = 0; rr < 4; rr++) {
            int r = bidx*4 + rr;
            const float* src = (r < BSROWS) ? (from_t + r*DMODEL)
                                            : (to_t + (r - BSROWS)*DMODEL);
            f[rr] = *(const float4*)&src[c4*4];
        }
        #pragma unroll
        for (int rr = 0; rr < 4; rr++) {
            int r = bidx*4 + rr;
            *(uint2*)&g_x[r*KPD + c4*2] =
                make_uint2(round_pair_h(f[rr].x, f[rr].y), round_pair_h(f[rr].z, f[rr].w));
        }
    } else if (bidx < 2816) {
        // --- pack W (64k x 64n tile with smem transpose) ---
        int idx = bidx - 2048;          // 0..767
        int z   = idx >> 8;             // /256
        int rem = idx & 255;
        int kt  = (rem >> 4) * 64;
        int nt  = (rem & 15) * 64;
        const float* W = (z == 0) ? Wq : (z == 1 ? Wk : Wv);

        #pragma unroll
        for (int p = 0; p < 4; p++) {
            int i2 = threadIdx.x + p*256;
            int kr = i2 >> 4;
            int c4 = (i2 & 15) * 4;
            float4 v = *(const float4*)&W[(kt+kr)*DMODEL + nt + c4];
            T[kr][c4+0] = v.x; T[kr][c4+1] = v.y;
            T[kr][c4+2] = v.z; T[kr][c4+3] = v.w;
        }
        __syncthreads();

        const int kt2 = kt >> 1;
        #pragma unroll
        for (int p = 0; p < 8; p++) {
            int o = threadIdx.x + p*256;
            int n  = o >> 5;
            int kp = o & 31;
            int gidx = (z*DMODEL + nt + n)*KPD + kt2 + kp;
            g_w[gidx] = round_pair_h(T[2*kp][n], T[2*kp+1][n]);
        }
    } else {
        // --- mask flags ---
        int idx = bidx - 2816;          // 0..1023
        int b   = idx >> 9;             // /512
        int rem = idx & 511;
        int fy  = rem >> 5;             // f-tile 0..15
        int tx  = rem & 31;             // t-chunk 0..31
        int f   = fy*128 + (threadIdx.x >> 1);
        int tc  = tx*64  + (threadIdx.x & 1)*32;
        const int4* p = (const int4*)&mask[(b*SEQ + f)*SEQ + tc];
        int ok = 1;
        #pragma unroll
        for (int i = 0; i < 8; i++) {
            int4 v = p[i];
            ok &= (v.x == 1) & (v.y == 1) & (v.z == 1) & (v.w == 1);
        }
        ok = __syncthreads_and(ok);
        if (threadIdx.x == 0)
            g_mflag[(b*16 + fy)*32 + tx] = (unsigned char)ok;
    }
}

// ---------------------------------------------------------------------------
// Kernel: QKV projection GEMM, pure fp16 (fp32 accum), depth-2 cp.async ring.
// Block 128m x 64n, 8 warps (4m x 2n), warp 32x32, K-step 32.
// Stage: X 128x20 | W 64x20 = 3840 u32; 3 stages. Q pre-scaled by SCALE_L2.
// ---------------------------------------------------------------------------
#define PSTG 3840
#define PB_H 2560

__global__ __launch_bounds__(256, 3) void qkv_proj_kernel(
    const float* __restrict__ bq, const float* __restrict__ bk,
    const float* __restrict__ bv)
{
    extern __shared__ uint32_t dsm[];

    const int z = blockIdx.z;
    const uint32_t* Xp = g_x + (z == 0 ? 0 : BSROWS*KPD);
    const uint32_t* Wp = g_w + z*DMODEL*KPD;
    const float* bias  = (z == 0) ? bq : (z == 1 ? bk : bv);
    uint32_t* dst      = (z == 0) ? g_q : (z == 1 ? g_k : g_v);
    const float oscale = (z == 0) ? SCALE_L2 : 1.0f;

    const int m0 = blockIdx.y * 128;
    const int n0 = blockIdx.x * 64;
    const int tid  = threadIdx.x;
    const int wid  = tid >> 5;
    const int lane = tid & 31;
    const int g  = lane >> 2;
    const int tg = lane & 3;
    const int wm = (wid >> 1) * 32;
    const int wn = (wid & 1) * 32;

    const int ar = tid >> 2;          // row 0..63 (A also +64)
    const int aq = (tid & 3) * 4;     // uint4 col within 16 k-pairs

    const int koffA = (lane & 15)*20 + (lane >> 4)*4;
    const uint32_t sBase = (uint32_t)__cvta_generic_to_shared(dsm);

    auto prefetch = [&](int stage, int kq) {
        uint32_t sb = sBase + (uint32_t)(stage * PSTG) * 4u;
        cp16(sb + (ar*20 + aq)*4u,        &Xp[(m0+ar)*KPD + kq + aq]);
        cp16(sb + ((ar+64)*20 + aq)*4u,   &Xp[(m0+ar+64)*KPD + kq + aq]);
        cp16(sb + (PB_H + ar*20 + aq)*4u, &Wp[(n0+ar)*KPD + kq + aq]);
    };

    float acc[2][4][4] = {};

    // depth-2 prologue
    prefetch(0, 0);  cp_commit();
    prefetch(1, 16); cp_commit();

    for (int it = 0; it < 32; it++) {
        cp_wait1();          // all but newest group done -> stage it ready
        __syncthreads();     // all warps done reading stage (it-1)%3
        if (it + 2 < 32) prefetch((it + 2) % 3, (it + 2) * 16);
        cp_commit();         // unconditional: uniform group accounting

        const uint32_t aB = sBase + (uint32_t)((it % 3) * PSTG) * 4u;
        #pragma unroll
        for (int ks = 0; ks < 2; ks++) {
            int kb = ks * 8;
            uint32_t ah[2][4], bh[2][4];
            #pragma unroll
            for (int mi = 0; mi < 2; mi++) {
                uint32_t off = (uint32_t)((wm + mi*16)*20 + kb + koffA) * 4u;
                ldsm_x4(ah[mi][0], ah[mi][1], ah[mi][2], ah[mi][3], aB + off);
            }
            #pragma unroll
            for (int nip = 0; nip < 2; nip++) {
                uint32_t off = (uint32_t)((wn + nip*16)*20 + kb + koffA) * 4u;
                ldsm_x4(bh[nip][0], bh[nip][1], bh[nip][2], bh[nip][3], aB + PB_H*4u + off);
            }
            #pragma unroll
            for (int nip = 0; nip < 2; nip++) {
                #pragma unroll
                for (int j = 0; j < 2; j++) {
                    int ni = nip*2 + j;
                    #pragma unroll
                    for (int mi = 0; mi < 2; mi++) {
                        mma_f16(acc[mi][ni], ah[mi][0],ah[mi][1],ah[mi][2],ah[mi][3],
                                bh[nip][j], bh[nip][2+j]);
                    }
                }
            }
        }
        // no bottom barrier: next iter's top barrier guards stage reuse
    }

    __syncthreads();
    // --- epilogue: bias (+ Q scale fold), round to fp16 pairs, write scratch ---
    const int head = n0 >> 6;
    #pragma unroll
    for (int ni = 0; ni < 4; ni++) {
        int h = wn + ni*8 + 2*tg;
        int hp = h >> 1;
        float2 b2 = *(const float2*)&bias[n0 + h];
        #pragma unroll
        for (int mi = 0; mi < 2; mi++) {
            int r0 = m0 + wm + mi*16 + g;
            int r1 = r0 + 8;
            int b0i = r0 >> 11, s0 = r0 & (SEQ-1);
            int b1i = r1 >> 11, s1 = r1 & (SEQ-1);
            size_t i0 = ((size_t)(b0i*NHEADS + head)*SEQ + s0)*HP + hp;
            size_t i1 = ((size_t)(b1i*NHEADS + head)*SEQ + s1)*HP + hp;
            dst[i0] = round_pair_h((acc[mi][ni][0] + b2.x) * oscale,
                                   (acc[mi][ni][1] + b2.y) * oscale);
            dst[i1] = round_pair_h((acc[mi][ni][2] + b2.x) * oscale,
                                   (acc[mi][ni][3] + b2.y) * oscale);
        }
    }
}

// ---------------------------------------------------------------------------
// Kernel: flash attention, pure fp16 (fp32 accum), depth-2 cp.async ring.
// Q pre-scaled -> S lands in log2 domain; softmax via ex2.approx.
// Stage: K 64x36 | V 64x36 = 4608 u32; 3 stages.
// ---------------------------------------------------------------------------
#define ASTG 4608
#define A_VH 2304

__global__ __launch_bounds__(256, 2) void attn_kernel(
    const int* __restrict__ mask, float* __restrict__ out)
{
    extern __shared__ uint32_t asm_dsm[];

    const int f0   = blockIdx.x * 128;
    const int head = blockIdx.y;
    const int b    = blockIdx.z;
    const int bh   = b*NHEADS + head;
    const int tid  = threadIdx.x;
    const int lane = tid & 31;
    const int g  = lane >> 2;
    const int tg = lane & 3;
    const int fb = (tid >> 5) * 16;

    const int frow0 = f0 + fb + g;
    const int frow1 = frow0 + 8;

    const int koffK = ((((lane>>4)&1)*8 + (lane&7))*36 + ((lane>>3)&1)*4);
    const int koffV = ((((lane>>3)&1)*8 + (lane&7))*36 + ((lane>>4)&1)*4);

    const uint32_t sBase = (uint32_t)__cvta_generic_to_shared(asm_dsm);

    // --- preload Q fragments (pre-scaled by SCALE_L2) ---
    uint32_t qh[4][4];
    {
        const uint32_t* qp = g_q + bh*SEQ*HP;
        int q0 = frow0*HP, q1 = frow1*HP;
        #pragma unroll
        for (int ks = 0; ks < 4; ks++) {
            int kb = ks*8 + tg;
            qh[ks][0] = qp[q0 + kb];   qh[ks][1] = qp[q1 + kb];
            qh[ks][2] = qp[q0 + kb+4]; qh[ks][3] = qp[q1 + kb+4];
        }
    }

    const uint32_t* kb_g = g_k + bh*SEQ*HP;
    const uint32_t* vb_g = g_v + bh*SEQ*HP;
    const unsigned char* mfl = &g_mflag[(b*16 + blockIdx.x)*32];

    float m0 = -1e30f, m1 = -1e30f;       // log2-domain row maxes
    float l0s = 0.0f, l1s = 0.0f;
    float O[8][4] = {};

    const int cr  = tid >> 3;        // 0..31 -> rows cr, cr+32
    const int cc4 = (tid & 7) * 4;

    auto prefetch = [&](int stage, int t0) {
        uint32_t sb = sBase + (uint32_t)(stage * ASTG) * 4u;
        cp16(sb + (cr*36 + cc4)*4u,               &kb_g[(t0+cr)*HP + cc4]);
        cp16(sb + ((cr+32)*36 + cc4)*4u,          &kb_g[(t0+cr+32)*HP + cc4]);
        cp16(sb + (A_VH + cr*36 + cc4)*4u,        &vb_g[(t0+cr)*HP + cc4]);
        cp16(sb + (A_VH + (cr+32)*36 + cc4)*4u,   &vb_g[(t0+cr+32)*HP + cc4]);
    };

    // depth-2 prologue
    prefetch(0, 0);   cp_commit();
    prefetch(1, 64);  cp_commit();

    for (int it = 0; it < SEQ/64; it++) {
        const int t0 = it * 64;
        cp_wait1();
        __syncthreads();
        if (it + 2 < SEQ/64) prefetch((it + 2) % 3, t0 + 128);
        cp_commit();

        const uint32_t sb = sBase + (uint32_t)((it % 3) * ASTG) * 4u;
        const uint32_t khB = sb;
        const uint32_t vhB = sb + A_VH*4u;

        // --- S = Q K^T (already log2-scaled) ---
        float s[8][4] = {};
        #pragma unroll
        for (int ks = 0; ks < 4; ks++) {
            int kb = ks * 8;
            #pragma unroll
            for (int ntp = 0; ntp < 4; ntp++) {
                uint32_t off = (uint32_t)(ntp*16*36 + koffK + kb) * 4u;
                uint32_t k0,k1,k2,k3;
                ldsm_x4(k0,k1,k2,k3, khB + off);
                mma_f16(s[2*ntp],   qh[ks][0],qh[ks][1],qh[ks][2],qh[ks][3], k0, k1);
                mma_f16(s[2*ntp+1], qh[ks][0],qh[ks][1],qh[ks][2],qh[ks][3], k2, k3);
            }
        }

        // --- mask (skippable; additive only) + chunk row max ---
        float rmax0 = -1e30f, rmax1 = -1e30f;
        if (mfl[it]) {
            #pragma unroll
            for (int nt = 0; nt < 8; nt++) {
                rmax0 = fmaxf(rmax0, fmaxf(s[nt][0], s[nt][1]));
                rmax1 = fmaxf(rmax1, fmaxf(s[nt][2], s[nt][3]));
            }
        } else {
            #pragma unroll
            for (int nt = 0; nt < 8; nt++) {
                int tc = t0 + nt*8 + 2*tg;
                int2 mk0 = *(const int2*)&mask[(b*SEQ + frow0)*SEQ + tc];
                int2 mk1 = *(const int2*)&mask[(b*SEQ + frow1)*SEQ + tc];
                s[nt][0] += (1.0f - (float)mk0.x) * MASKM_L2;
                s[nt][1] += (1.0f - (float)mk0.y) * MASKM_L2;
                s[nt][2] += (1.0f - (float)mk1.x) * MASKM_L2;
                s[nt][3] += (1.0f - (float)mk1.y) * MASKM_L2;
                rmax0 = fmaxf(rmax0, fmaxf(s[nt][0], s[nt][1]));
                rmax1 = fmaxf(rmax1, fmaxf(s[nt][2], s[nt][3]));
            }
        }
        rmax0 = fmaxf(rmax0, __shfl_xor_sync(0xffffffffu, rmax0, 1));
        rmax0 = fmaxf(rmax0, __shfl_xor_sync(0xffffffffu, rmax0, 2));
        rmax1 = fmaxf(rmax1, __shfl_xor_sync(0xffffffffu, rmax1, 1));
        rmax1 = fmaxf(rmax1, __shfl_xor_sync(0xffffffffu, rmax1, 2));

        float mn0 = fmaxf(m0, rmax0), mn1 = fmaxf(m1, rmax1);
        float a0 = fast_exp2(m0 - mn0),  a1 = fast_exp2(m1 - mn1);
        m0 = mn0; m1 = mn1;

        // --- exp2 + round P fragments to fp16 in registers ---
        uint32_t ph0[8], ph1[8];
        float ps0 = 0.0f, ps1 = 0.0f;
        #pragma unroll
        for (int nt = 0; nt < 8; nt++) {
            float p00 = fast_exp2(s[nt][0] - mn0);
            float p01 = fast_exp2(s[nt][1] - mn0);
            float p10 = fast_exp2(s[nt][2] - mn1);
            float p11 = fast_exp2(s[nt][3] - mn1);
            ps0 += p00 + p01;
            ps1 += p10 + p11;
            ph0[nt] = round_pair_h(p00, p01);
            ph1[nt] = round_pair_h(p10, p11);
        }
        ps0 += __shfl_xor_sync(0xffffffffu, ps0, 1);
        ps0 += __shfl_xor_sync(0xffffffffu, ps0, 2);
        ps1 += __shfl_xor_sync(0xffffffffu, ps1, 1);
        ps1 += __shfl_xor_sync(0xffffffffu, ps1, 2);
        l0s = l0s * a0 + ps0;
        l1s = l1s * a1 + ps1;

        #pragma unroll
        for (int ht = 0; ht < 8; ht++) {
            O[ht][0] *= a0; O[ht][1] *= a0;
            O[ht][2] *= a1; O[ht][3] *= a1;
        }

        // --- O += P V ---
        #pragma unroll
        for (int ks = 0; ks < 4; ks++) {
            uint32_t ah0 = ph0[2*ks],   ah1 = ph1[2*ks];
            uint32_t ah2 = ph0[2*ks+1], ah3 = ph1[2*ks+1];
            #pragma unroll
            for (int htp = 0; htp < 4; htp++) {
                uint32_t off = (uint32_t)(ks*16*36 + htp*8 + koffV) * 4u;
                uint32_t v0,v1,v2,v3;
                ldsm_x4_trans(v0,v1,v2,v3, vhB + off);
                mma_f16(O[2*htp],   ah0,ah1,ah2,ah3, v0, v1);
                mma_f16(O[2*htp+1], ah0,ah1,ah2,ah3, v2, v3);
            }
        }
    }

    float inv0 = 1.0f / l0s;
    float inv1 = 1.0f / l1s;
    #pragma unroll
    for (int ht = 0; ht < 8; ht++) {
        int h = ht*8 + 2*tg;
        float2 r0 = make_float2(O[ht][0]*inv0, O[ht][1]*inv0);
        float2 r1 = make_float2(O[ht][2]*inv1, O[ht][3]*inv1);
        *(float2*)&out[(b*SEQ + frow0)*DMODEL + head*HDIM + h] = r0;
        *(float2*)&out[(b*SEQ + frow1)*DMODEL + head*HDIM + h] = r1;
    }
}

// ---------------------------------------------------------------------------
extern "C" void kernel_launch(void* const* d_in, const int* in_sizes, int n_in,
                              void* d_out, int out_size)
{
    const float* from_t = (const float*)d_in[0];
    const float* to_t   = (const float*)d_in[1];
    const int*   mask   = (const int*)  d_in[2];
    const float* Wq = (const float*)d_in[3];
    const float* bq = (const float*)d_in[4];
    const float* Wk = (const float*)d_in[5];
    const float* bk = (const float*)d_in[6];
    const float* Wv = (const float*)d_in[7];
    const float* bv = (const float*)d_in[8];
    float* out = (float*)d_out;

    prep_kernel<<<3840, 256>>>(from_t, to_t, Wq, Wk, Wv, mask);

    const int proj_smem = 3 * PSTG * 4;   // 46080 B
    cudaFuncSetAttribute(qkv_proj_kernel,
                         cudaFuncAttributeMaxDynamicSharedMemorySize, proj_smem);
    dim3 pgrid(DMODEL/64, BSROWS/128, 3);
    qkv_proj_kernel<<<pgrid, 256, proj_smem>>>(bq, bk, bv);

    const int attn_smem = 3 * ASTG * 4;   // 55296 B
    cudaFuncSetAttribute(attn_kernel,
                         cudaFuncAttributeMaxDynamicSharedMemorySize, attn_smem);
    dim3 agrid(SEQ/128, NHEADS, BATCH);
    attn_kernel<<<agrid, 256, attn_smem>>>(mask, out);
}

// round 17
// speedup vs baseline: 1.0850x; 1.0265x over previous
#include <cuda_runtime.h>
#include <cuda_fp16.h>
#include <cstdint>

#define NHEADS 16
#define HDIM   64
#define DMODEL 1024
#define BATCH  2
#define SEQ    2048
#define BSROWS 4096          // BATCH*SEQ
#define HP     32            // HDIM/2  (fp16 pairs per head row)
#define KPD    512           // DMODEL/2

// --- packed fp16 global scratch ---------------------------------------------
__device__ uint32_t g_x[2*BSROWS*KPD];                           // from(0)+to(1), [m][k/2]
__device__ uint32_t g_w[3*DMODEL*KPD];                           // [z][n][k/2]
__device__ uint32_t g_q[BATCH*NHEADS*SEQ*HP];                    // [bh][s][h/2], pre-scaled
__device__ uint32_t g_k[BATCH*NHEADS*SEQ*HP];
__device__ uint32_t g_v[BATCH*NHEADS*SEQ*HP];
__device__ unsigned char g_mflag[BATCH*16*32];   // [b][f-tile(128)][t-chunk(64)]

// log2 domain constants (softmax computed with ex2; scale folded into Q)
#define SCALE_L2 0.18033688011111043f     // 0.125 * log2(e)
#define MASKM_L2 -14426.950408889634f     // -10000 * log2(e)

// ---------------------------------------------------------------------------
__device__ __forceinline__ uint32_t round_pair_h(float x, float y)
{
    __half2 h2 = __halves2half2(__float2half_rn(x), __float2half_rn(y));
    return *reinterpret_cast<uint32_t*>(&h2);
}

__device__ __forceinline__ float fast_exp2(float x)
{
    float r;
    asm("ex2.approx.f32 %0, %1;" : "=f"(r) : "f"(x));
    return r;
}

__device__ __forceinline__ void mma_f16(float* d,
    uint32_t a0, uint32_t a1, uint32_t a2, uint32_t a3,
    uint32_t b0, uint32_t b1)
{
    asm("mma.sync.aligned.m16n8k16.row.col.f32.f16.f16.f32 "
        "{%0,%1,%2,%3}, {%4,%5,%6,%7}, {%8,%9}, {%0,%1,%2,%3};\n"
        : "+f"(d[0]), "+f"(d[1]), "+f"(d[2]), "+f"(d[3])
        : "r"(a0), "r"(a1), "r"(a2), "r"(a3), "r"(b0), "r"(b1));
}

__device__ __forceinline__ void ldsm_x4(uint32_t& r0, uint32_t& r1,
                                        uint32_t& r2, uint32_t& r3, uint32_t addr)
{
    asm volatile("ldmatrix.sync.aligned.m8n8.x4.shared.b16 {%0,%1,%2,%3}, [%4];\n"
        : "=r"(r0), "=r"(r1), "=r"(r2), "=r"(r3) : "r"(addr));
}

__device__ __forceinline__ void ldsm_x4_trans(uint32_t& r0, uint32_t& r1,
                                              uint32_t& r2, uint32_t& r3, uint32_t addr)
{
    asm volatile("ldmatrix.sync.aligned.m8n8.x4.trans.shared.b16 {%0,%1,%2,%3}, [%4];\n"
        : "=r"(r0), "=r"(r1), "=r"(r2), "=r"(r3) : "r"(addr));
}

// ---- cp.async helpers ------------------------------------------------------
__device__ __forceinline__ void cp16(uint32_t dst_smem, const void* src)
{
    asm volatile("cp.async.cg.shared.global [%0], [%1], 16;"
                 :: "r"(dst_smem), "l"(src));
}
__device__ __forceinline__ void cp_commit()
{
    asm volatile("cp.async.commit_group;" ::: "memory");
}
__device__ __forceinline__ void cp_wait1()
{
    asm volatile("cp.async.wait_group 1;" ::: "memory");
}

// ---------------------------------------------------------------------------
// Prep kernel: X + W packing only (mask scan moved into proj launch).
//   blocks [0, 2048)       : pack X, 4 rows/block (MLP 4)
//   blocks [2048, 2816)    : pack W tiles -> transposed fp16 pairs
// ---------------------------------------------------------------------------
__global__ __launch_bounds__(256) void prep_kernel(
    const float* __restrict__ from_t, const float* __restrict__ to_t,
    const float* __restrict__ Wq, const float* __restrict__ Wk,
    const float* __restrict__ Wv)
{
    __shared__ float T[64][65];
    const int bidx = blockIdx.x;

    if (bidx < 2048) {
        // --- pack X: rows 4*bidx .. 4*bidx+3 (independent loads -> MLP 4) ---
        int c4 = threadIdx.x;
        float4 f[4];
        #pragma unroll
        for (int rr = 0; rr < 4; rr++) {
            int r = bidx*4 + rr;
            const float* src = (r < BSROWS) ? (from_t + r*DMODEL)
                                            : (to_t + (r - BSROWS)*DMODEL);
            f[rr] = *(const float4*)&src[c4*4];
        }
        #pragma unroll
        for (int rr = 0; rr < 4; rr++) {
            int r = bidx*4 + rr;
            *(uint2*)&g_x[r*KPD + c4*2] =
                make_uint2(round_pair_h(f[rr].x, f[rr].y), round_pair_h(f[rr].z, f[rr].w));
        }
    } else {
        // --- pack W (64k x 64n tile with smem transpose) ---
        int idx = bidx - 2048;          // 0..767
        int z   = idx >> 8;             // /256
        int rem = idx & 255;
        int kt  = (rem >> 4) * 64;
        int nt  = (rem & 15) * 64;
        const float* W = (z == 0) ? Wq : (z == 1 ? Wk : Wv);

        #pragma unroll
        for (int p = 0; p < 4; p++) {
            int i2 = threadIdx.x + p*256;
            int kr = i2 >> 4;
            int c4 = (i2 & 15) * 4;
            float4 v = *(const float4*)&W[(kt+kr)*DMODEL + nt + c4];
            T[kr][c4+0] = v.x; T[kr][c4+1] = v.y;
            T[kr][c4+2] = v.z; T[kr][c4+3] = v.w;
        }
        __syncthreads();

        const int kt2 = kt >> 1;
        #pragma unroll
        for (int p = 0; p < 8; p++) {
            int o = threadIdx.x + p*256;
            int n  = o >> 5;
            int kp = o & 31;
            int gidx = (z*DMODEL + nt + n)*KPD + kt2 + kp;
            g_w[gidx] = round_pair_h(T[2*kp][n], T[2*kp+1][n]);
        }
    }
}

// ---------------------------------------------------------------------------
// Kernel: QKV projection GEMM (z<3) + mask-flag scan riding along (z==3).
// GEMM: pure fp16 (fp32 accum), depth-2 cp.async ring, block 128m x 64n.
// Stage: X 128x20 | W 64x20 = 3840 u32; 3 stages. Q pre-scaled by SCALE_L2.
// z==3: 512 blocks x 2 mask tiles each (scan overlaps GEMM compute).
// ---------------------------------------------------------------------------
#define PSTG 3840
#define PB_H 2560

__global__ __launch_bounds__(256, 3) void qkv_proj_kernel(
    const float* __restrict__ bq, const float* __restrict__ bk,
    const float* __restrict__ bv, const int* __restrict__ mask)
{
    extern __shared__ uint32_t dsm[];

    const int z = blockIdx.z;
    if (z == 3) {
        // --- mask-flag scan: 2 tiles per block ---
        int base = (blockIdx.y * 16 + blockIdx.x) * 2;   // 0..1022
        #pragma unroll
        for (int tt = 0; tt < 2; tt++) {
            int idx = base + tt;           // 0..1023
            int b   = idx >> 9;
            int rem = idx & 511;
            int fy  = rem >> 5;
            int tx  = rem & 31;
            int f   = fy*128 + (threadIdx.x >> 1);
            int tc  = tx*64  + (threadIdx.x & 1)*32;
            const int4* p = (const int4*)&mask[(b*SEQ + f)*SEQ + tc];
            int ok = 1;
            #pragma unroll
            for (int i = 0; i < 8; i++) {
                int4 v = p[i];
                ok &= (v.x == 1) & (v.y == 1) & (v.z == 1) & (v.w == 1);
            }
            ok = __syncthreads_and(ok);
            if (threadIdx.x == 0)
                g_mflag[(b*16 + fy)*32 + tx] = (unsigned char)ok;
        }
        return;
    }

    const uint32_t* Xp = g_x + (z == 0 ? 0 : BSROWS*KPD);
    const uint32_t* Wp = g_w + z*DMODEL*KPD;
    const float* bias  = (z == 0) ? bq : (z == 1 ? bk : bv);
    uint32_t* dst      = (z == 0) ? g_q : (z == 1 ? g_k : g_v);
    const float oscale = (z == 0) ? SCALE_L2 : 1.0f;

    const int m0 = blockIdx.y * 128;
    const int n0 = blockIdx.x * 64;
    const int tid  = threadIdx.x;
    const int wid  = tid >> 5;
    const int lane = tid & 31;
    const int g  = lane >> 2;
    const int tg = lane & 3;
    const int wm = (wid >> 1) * 32;
    const int wn = (wid & 1) * 32;

    const int ar = tid >> 2;          // row 0..63 (A also +64)
    const int aq = (tid & 3) * 4;     // uint4 col within 16 k-pairs

    const int koffA = (lane & 15)*20 + (lane >> 4)*4;
    const uint32_t sBase = (uint32_t)__cvta_generic_to_shared(dsm);

    auto prefetch = [&](int stage, int kq) {
        uint32_t sb = sBase + (uint32_t)(stage * PSTG) * 4u;
        cp16(sb + (ar*20 + aq)*4u,        &Xp[(m0+ar)*KPD + kq + aq]);
        cp16(sb + ((ar+64)*20 + aq)*4u,   &Xp[(m0+ar+64)*KPD + kq + aq]);
        cp16(sb + (PB_H + ar*20 + aq)*4u, &Wp[(n0+ar)*KPD + kq + aq]);
    };

    float acc[2][4][4] = {};

    // depth-2 prologue
    prefetch(0, 0);  cp_commit();
    prefetch(1, 16); cp_commit();

    for (int it = 0; it < 32; it++) {
        cp_wait1();          // all but newest group done -> stage it ready
        __syncthreads();     // all warps done reading stage (it-1)%3
        if (it + 2 < 32) prefetch((it + 2) % 3, (it + 2) * 16);
        cp_commit();         // unconditional: uniform group accounting

        const uint32_t aB = sBase + (uint32_t)((it % 3) * PSTG) * 4u;
        #pragma unroll
        for (int ks = 0; ks < 2; ks++) {
            int kb = ks * 8;
            uint32_t ah[2][4], bh[2][4];
            #pragma unroll
            for (int mi = 0; mi < 2; mi++) {
                uint32_t off = (uint32_t)((wm + mi*16)*20 + kb + koffA) * 4u;
                ldsm_x4(ah[mi][0], ah[mi][1], ah[mi][2], ah[mi][3], aB + off);
            }
            #pragma unroll
            for (int nip = 0; nip < 2; nip++) {
                uint32_t off = (uint32_t)((wn + nip*16)*20 + kb + koffA) * 4u;
                ldsm_x4(bh[nip][0], bh[nip][1], bh[nip][2], bh[nip][3], aB + PB_H*4u + off);
            }
            #pragma unroll
            for (int nip = 0; nip < 2; nip++) {
                #pragma unroll
                for (int j = 0; j < 2; j++) {
                    int ni = nip*2 + j;
                    #pragma unroll
                    for (int mi = 0; mi < 2; mi++) {
                        mma_f16(acc[mi][ni], ah[mi][0],ah[mi][1],ah[mi][2],ah[mi][3],
                                bh[nip][j], bh[nip][2+j]);
                    }
                }
            }
        }
        // no bottom barrier: next iter's top barrier guards stage reuse
    }

    __syncthreads();
    // --- epilogue: bias (+ Q scale fold), round to fp16 pairs, write scratch ---
    const int head = n0 >> 6;
    #pragma unroll
    for (int ni = 0; ni < 4; ni++) {
        int h = wn + ni*8 + 2*tg;
        int hp = h >> 1;
        float2 b2 = *(const float2*)&bias[n0 + h];
        #pragma unroll
        for (int mi = 0; mi < 2; mi++) {
            int r0 = m0 + wm + mi*16 + g;
            int r1 = r0 + 8;
            int b0i = r0 >> 11, s0 = r0 & (SEQ-1);
            int b1i = r1 >> 11, s1 = r1 & (SEQ-1);
            size_t i0 = ((size_t)(b0i*NHEADS + head)*SEQ + s0)*HP + hp;
            size_t i1 = ((size_t)(b1i*NHEADS + head)*SEQ + s1)*HP + hp;
            dst[i0] = round_pair_h((acc[mi][ni][0] + b2.x) * oscale,
                                   (acc[mi][ni][1] + b2.y) * oscale);
            dst[i1] = round_pair_h((acc[mi][ni][2] + b2.x) * oscale,
                                   (acc[mi][ni][3] + b2.y) * oscale);
        }
    }
}

// ---------------------------------------------------------------------------
// Kernel: flash attention, pure fp16 (fp32 accum), depth-2 cp.async ring.
// Q pre-scaled -> S lands in log2 domain; softmax via ex2.approx.
// Stage: K 64x36 | V 64x36 = 4608 u32; 3 stages.
// ---------------------------------------------------------------------------
#define ASTG 4608
#define A_VH 2304

__global__ __launch_bounds__(256, 2) void attn_kernel(
    const int* __restrict__ mask, float* __restrict__ out)
{
    extern __shared__ uint32_t asm_dsm[];

    const int f0   = blockIdx.x * 128;
    const int head = blockIdx.y;
    const int b    = blockIdx.z;
    const int bh   = b*NHEADS + head;
    const int tid  = threadIdx.x;
    const int lane = tid & 31;
    const int g  = lane >> 2;
    const int tg = lane & 3;
    const int fb = (tid >> 5) * 16;

    const int frow0 = f0 + fb + g;
    const int frow1 = frow0 + 8;

    const int koffK = ((((lane>>4)&1)*8 + (lane&7))*36 + ((lane>>3)&1)*4);
    const int koffV = ((((lane>>3)&1)*8 + (lane&7))*36 + ((lane>>4)&1)*4);

    const uint32_t sBase = (uint32_t)__cvta_generic_to_shared(asm_dsm);

    // --- preload Q fragments (pre-scaled by SCALE_L2) ---
    uint32_t qh[4][4];
    {
        const uint32_t* qp = g_q + bh*SEQ*HP;
        int q0 = frow0*HP, q1 = frow1*HP;
        #pragma unroll
        for (int ks = 0; ks < 4; ks++) {
            int kb = ks*8 + tg;
            qh[ks][0] = qp[q0 + kb];   qh[ks][1] = qp[q1 + kb];
            qh[ks][2] = qp[q0 + kb+4]; qh[ks][3] = qp[q1 + kb+4];
        }
    }

    const uint32_t* kb_g = g_k + bh*SEQ*HP;
    const uint32_t* vb_g = g_v + bh*SEQ*HP;
    const unsigned char* mfl = &g_mflag[(b*16 + blockIdx.x)*32];

    float m0 = -1e30f, m1 = -1e30f;       // log2-domain row maxes
    float l0s = 0.0f, l1s = 0.0f;
    float O[8][4] = {};

    const int cr  = tid >> 3;        // 0..31 -> rows cr, cr+32
    const int cc4 = (tid & 7) * 4;

    auto prefetch = [&](int stage, int t0) {
        uint32_t sb = sBase + (uint32_t)(stage * ASTG) * 4u;
        cp16(sb + (cr*36 + cc4)*4u,               &kb_g[(t0+cr)*HP + cc4]);
        cp16(sb + ((cr+32)*36 + cc4)*4u,          &kb_g[(t0+cr+32)*HP + cc4]);
        cp16(sb + (A_VH + cr*36 + cc4)*4u,        &vb_g[(t0+cr)*HP + cc4]);
        cp16(sb + (A_VH + (cr+32)*36 + cc4)*4u,   &vb_g[(t0+cr+32)*HP + cc4]);
    };

    // depth-2 prologue
    prefetch(0, 0);   cp_commit();
    prefetch(1, 64);  cp_commit();

    for (int it = 0; it < SEQ/64; it++) {
        const int t0 = it * 64;
        cp_wait1();
        __syncthreads();
        if (it + 2 < SEQ/64) prefetch((it + 2) % 3, t0 + 128);
        cp_commit();

        const uint32_t sb = sBase + (uint32_t)((it % 3) * ASTG) * 4u;
        const uint32_t khB = sb;
        const uint32_t vhB = sb + A_VH*4u;

        // --- S = Q K^T (already log2-scaled) ---
        float s[8][4] = {};
        #pragma unroll
        for (int ks = 0; ks < 4; ks++) {
            int kb = ks * 8;
            #pragma unroll
            for (int ntp = 0; ntp < 4; ntp++) {
                uint32_t off = (uint32_t)(ntp*16*36 + koffK + kb) * 4u;
                uint32_t k0,k1,k2,k3;
                ldsm_x4(k0,k1,k2,k3, khB + off);
                mma_f16(s[2*ntp],   qh[ks][0],qh[ks][1],qh[ks][2],qh[ks][3], k0, k1);
                mma_f16(s[2*ntp+1], qh[ks][0],qh[ks][1],qh[ks][2],qh[ks][3], k2, k3);
            }
        }

        // --- mask (skippable; additive only) + chunk row max ---
        float rmax0 = -1e30f, rmax1 = -1e30f;
        if (mfl[it]) {
            #pragma unroll
            for (int nt = 0; nt < 8; nt++) {
                rmax0 = fmaxf(rmax0, fmaxf(s[nt][0], s[nt][1]));
                rmax1 = fmaxf(rmax1, fmaxf(s[nt][2], s[nt][3]));
            }
        } else {
            #pragma unroll
            for (int nt = 0; nt < 8; nt++) {
                int tc = t0 + nt*8 + 2*tg;
                int2 mk0 = *(const int2*)&mask[(b*SEQ + frow0)*SEQ + tc];
                int2 mk1 = *(const int2*)&mask[(b*SEQ + frow1)*SEQ + tc];
                s[nt][0] += (1.0f - (float)mk0.x) * MASKM_L2;
                s[nt][1] += (1.0f - (float)mk0.y) * MASKM_L2;
                s[nt][2] += (1.0f - (float)mk1.x) * MASKM_L2;
                s[nt][3] += (1.0f - (float)mk1.y) * MASKM_L2;
                rmax0 = fmaxf(rmax0, fmaxf(s[nt][0], s[nt][1]));
                rmax1 = fmaxf(rmax1, fmaxf(s[nt][2], s[nt][3]));
            }
        }
        rmax0 = fmaxf(rmax0, __shfl_xor_sync(0xffffffffu, rmax0, 1));
        rmax0 = fmaxf(rmax0, __shfl_xor_sync(0xffffffffu, rmax0, 2));
        rmax1 = fmaxf(rmax1, __shfl_xor_sync(0xffffffffu, rmax1, 1));
        rmax1 = fmaxf(rmax1, __shfl_xor_sync(0xffffffffu, rmax1, 2));

        float mn0 = fmaxf(m0, rmax0), mn1 = fmaxf(m1, rmax1);
        float a0 = fast_exp2(m0 - mn0),  a1 = fast_exp2(m1 - mn1);
        m0 = mn0; m1 = mn1;

        // --- exp2 + round P fragments to fp16 in registers ---
        uint32_t ph0[8], ph1[8];
        float ps0 = 0.0f, ps1 = 0.0f;
        #pragma unroll
        for (int nt = 0; nt < 8; nt++) {
            float p00 = fast_exp2(s[nt][0] - mn0);
            float p01 = fast_exp2(s[nt][1] - mn0);
            float p10 = fast_exp2(s[nt][2] - mn1);
            float p11 = fast_exp2(s[nt][3] - mn1);
            ps0 += p00 + p01;
            ps1 += p10 + p11;
            ph0[nt] = round_pair_h(p00, p01);
            ph1[nt] = round_pair_h(p10, p11);
        }
        ps0 += __shfl_xor_sync(0xffffffffu, ps0, 1);
        ps0 += __shfl_xor_sync(0xffffffffu, ps0, 2);
        ps1 += __shfl_xor_sync(0xffffffffu, ps1, 1);
        ps1 += __shfl_xor_sync(0xffffffffu, ps1, 2);
        l0s = l0s * a0 + ps0;
        l1s = l1s * a1 + ps1;

        #pragma unroll
        for (int ht = 0; ht < 8; ht++) {
            O[ht][0] *= a0; O[ht][1] *= a0;
            O[ht][2] *= a1; O[ht][3] *= a1;
        }

        // --- O += P V ---
        #pragma unroll
        for (int ks = 0; ks < 4; ks++) {
            uint32_t ah0 = ph0[2*ks],   ah1 = ph1[2*ks];
            uint32_t ah2 = ph0[2*ks+1], ah3 = ph1[2*ks+1];
            #pragma unroll
            for (int htp = 0; htp < 4; htp++) {
                uint32_t off = (uint32_t)(ks*16*36 + htp*8 + koffV) * 4u;
                uint32_t v0,v1,v2,v3;
                ldsm_x4_trans(v0,v1,v2,v3, vhB + off);
                mma_f16(O[2*htp],   ah0,ah1,ah2,ah3, v0, v1);
                mma_f16(O[2*htp+1], ah0,ah1,ah2,ah3, v2, v3);
            }
        }
    }

    float inv0 = 1.0f / l0s;
    float inv1 = 1.0f / l1s;
    #pragma unroll
    for (int ht = 0; ht < 8; ht++) {
        int h = ht*8 + 2*tg;
        float2 r0 = make_float2(O[ht][0]*inv0, O[ht][1]*inv0);
        float2 r1 = make_float2(O[ht][2]*inv1, O[ht][3]*inv1);
        *(float2*)&out[(b*SEQ + frow0)*DMODEL + head*HDIM + h] = r0;
        *(float2*)&out[(b*SEQ + frow1)*DMODEL + head*HDIM + h] = r1;
    }
}

// ---------------------------------------------------------------------------
extern "C" void kernel_launch(void* const* d_in, const int* in_sizes, int n_in,
                              void* d_out, int out_size)
{
    const float* from_t = (const float*)d_in[0];
    const float* to_t   = (const float*)d_in[1];
    const int*   mask   = (const int*)  d_in[2];
    const float* Wq = (const float*)d_in[3];
    const float* bq = (const float*)d_in[4];
    const float* Wk = (const float*)d_in[5];
    const float* bk = (const float*)d_in[6];
    const float* Wv = (const float*)d_in[7];
    const float* bv = (const float*)d_in[8];
    float* out = (float*)d_out;

    prep_kernel<<<2816, 256>>>(from_t, to_t, Wq, Wk, Wv);

    const int proj_smem = 3 * PSTG * 4;   // 46080 B
    cudaFuncSetAttribute(qkv_proj_kernel,
                         cudaFuncAttributeMaxDynamicSharedMemorySize, proj_smem);
    dim3 pgrid(DMODEL/64, BSROWS/128, 4);   // z<3: GEMM, z==3: mask scan
    qkv_proj_kernel<<<pgrid, 256, proj_smem>>>(bq, bk, bv, mask);

    const int attn_smem = 3 * ASTG * 4;   // 55296 B
    cudaFuncSetAttribute(attn_kernel,
                         cudaFuncAttributeMaxDynamicSharedMemorySize, attn_smem);
    dim3 agrid(SEQ/128, NHEADS, BATCH);
    attn_kernel<<<agrid, 256, attn_smem>>>(mask, out);
}